// round 4
// baseline (speedup 1.0000x reference)
#include <cuda_runtime.h>
#include <math.h>

#define MAXM 200000

// ---------------- static device scratch (no allocations allowed) ----------------
__device__ float g_acc[3 * MAXM * 5];              // per-scale [M,4] sums + count
__device__ float g_x[3 * MAXM * 4];                // scatter-mean outputs
__device__ float g_t64[MAXM * 64];                 // layer1 out (reused per scale)
__device__ float g_t128[MAXM * 128];               // layer2 out (reused per scale)
__device__ float g_feat[(size_t)3 * MAXM * 256];   // layer3 out per scale (kept)
__device__ float g_fused[(size_t)MAXM * 768];      // concat features
__device__ float g_y[(size_t)MAXM * 256];          // final pre-BN
__device__ float g_stats[10 * 1536];               // 10 BN slots: [sum(C), sumsq(C)]
__device__ int   g_idx0[MAXM];
__device__ int   g_idx2[MAXM];

// ---------------- zero scratch ----------------
__global__ void zero_kernel() {
    const size_t n1 = (size_t)3 * MAXM * 5;
    const size_t n2 = 10 * 1536;
    const size_t total = n1 + n2;
    const size_t stride = (size_t)gridDim.x * blockDim.x;
    for (size_t i = (size_t)blockIdx.x * blockDim.x + threadIdx.x; i < total; i += stride) {
        if (i < n1) g_acc[i] = 0.0f;
        else        g_stats[i - n1] = 0.0f;
    }
}

// ---------------- scatter (sum + count) for all 3 scales ----------------
__global__ void scatter_kernel(const float* __restrict__ pts,
                               const int* __restrict__ inv0,
                               const int* __restrict__ inv1,
                               const int* __restrict__ inv2, int N) {
    int i = blockIdx.x * blockDim.x + threadIdx.x;
    if (i >= N) return;
    float4 p = reinterpret_cast<const float4*>(pts)[i];
    int m0 = inv0[i], m1 = inv1[i], m2 = inv2[i];
    float* a0 = g_acc + (size_t)m0 * 5;
    float* a1 = g_acc + (size_t)MAXM * 5 + (size_t)m1 * 5;
    float* a2 = g_acc + (size_t)2 * MAXM * 5 + (size_t)m2 * 5;
    atomicAdd(a0 + 0, p.x); atomicAdd(a0 + 1, p.y); atomicAdd(a0 + 2, p.z); atomicAdd(a0 + 3, p.w); atomicAdd(a0 + 4, 1.0f);
    atomicAdd(a1 + 0, p.x); atomicAdd(a1 + 1, p.y); atomicAdd(a1 + 2, p.z); atomicAdd(a1 + 3, p.w); atomicAdd(a1 + 4, 1.0f);
    atomicAdd(a2 + 0, p.x); atomicAdd(a2 + 1, p.y); atomicAdd(a2 + 2, p.z); atomicAdd(a2 + 3, p.w); atomicAdd(a2 + 4, 1.0f);
}

// ---------------- finish mean: x = sum / max(cnt,1) ----------------
__global__ void mean_kernel(int s, int M) {
    int i = blockIdx.x * blockDim.x + threadIdx.x;
    if (i >= M) return;
    const float* a = g_acc + (size_t)s * MAXM * 5 + (size_t)i * 5;
    float c = fmaxf(a[4], 1.0f);
    float* x = g_x + (size_t)s * MAXM * 4 + (size_t)i * 4;
    x[0] = a[0] / c; x[1] = a[1] / c; x[2] = a[2] / c; x[3] = a[3] / c;
}

// ---------------- generic NT SGEMM: C[m,n] = sum_k A[m,k]*W[n,k] ----------------
__global__ void sgemm_nt(const float* __restrict__ A, const float* __restrict__ W,
                         float* __restrict__ C, int M, int N, int K) {
    const int BM = 64, BN = 64, BK = 16;
    __shared__ float As[BK][68];
    __shared__ float Ws[BK][68];
    int bm = blockIdx.y * BM;
    int bn = blockIdx.x * BN;
    int tid = threadIdx.x;
    int tx = tid & 15;
    int ty = tid >> 4;
    float acc[4][4] = {};
    for (int k0 = 0; k0 < K; k0 += BK) {
        #pragma unroll
        for (int i = tid; i < BM * BK; i += 256) {
            int r = i >> 4, k = i & 15;
            int gm = bm + r, gk = k0 + k;
            As[k][r] = (gm < M && gk < K) ? A[(size_t)gm * K + gk] : 0.0f;
        }
        #pragma unroll
        for (int i = tid; i < BN * BK; i += 256) {
            int r = i >> 4, k = i & 15;
            int gn = bn + r, gk = k0 + k;
            Ws[k][r] = (gn < N && gk < K) ? W[(size_t)gn * K + gk] : 0.0f;
        }
        __syncthreads();
        #pragma unroll
        for (int k = 0; k < BK; k++) {
            float4 a = *reinterpret_cast<const float4*>(&As[k][ty * 4]);
            float4 w = *reinterpret_cast<const float4*>(&Ws[k][tx * 4]);
            float av[4] = {a.x, a.y, a.z, a.w};
            float wv[4] = {w.x, w.y, w.z, w.w};
            #pragma unroll
            for (int i = 0; i < 4; i++)
                #pragma unroll
                for (int j = 0; j < 4; j++)
                    acc[i][j] += av[i] * wv[j];
        }
        __syncthreads();
    }
    #pragma unroll
    for (int i = 0; i < 4; i++) {
        int gm = bm + ty * 4 + i;
        if (gm >= M) continue;
        #pragma unroll
        for (int j = 0; j < 4; j++) {
            int gn = bn + tx * 4 + j;
            if (gn < N) C[(size_t)gm * N + gn] = acc[i][j];
        }
    }
}

// ---------------- column stats: sum + sumsq (C <= 768) ----------------
__global__ void stats_kernel(const float* __restrict__ Y, int M, int C,
                             float* __restrict__ st) {
    float s0 = 0, s1 = 0, s2 = 0, q0 = 0, q1 = 0, q2 = 0;
    for (int r = blockIdx.x; r < M; r += gridDim.x) {
        const float* row = Y + (size_t)r * C;
        int c = threadIdx.x;
        if (c < C) { float v = row[c]; s0 += v; q0 += v * v; }
        c += 256;
        if (c < C) { float v = row[c]; s1 += v; q1 += v * v; }
        c += 256;
        if (c < C) { float v = row[c]; s2 += v; q2 += v * v; }
    }
    int c = threadIdx.x;
    if (c < C) { atomicAdd(&st[c], s0); atomicAdd(&st[C + c], q0); }
    c += 256;
    if (c < C) { atomicAdd(&st[c], s1); atomicAdd(&st[C + c], q1); }
    c += 256;
    if (c < C) { atomicAdd(&st[c], s2); atomicAdd(&st[C + c], q2); }
}

// ---------------- BN (training-mode, biased var) + ReLU ----------------
__global__ void bnrelu_kernel(const float* __restrict__ Y, float* __restrict__ Z,
                              int M, int C, const float* __restrict__ st,
                              const float* __restrict__ G, const float* __restrict__ B) {
    size_t total = (size_t)M * C;
    size_t stride = (size_t)gridDim.x * blockDim.x;
    float invM = 1.0f / (float)M;
    for (size_t i = (size_t)blockIdx.x * blockDim.x + threadIdx.x; i < total; i += stride) {
        int c = (int)(i % C);
        float m = st[c] * invM;
        float v = st[C + c] * invM - m * m;
        float sc = rsqrtf(fmaxf(v, 0.0f) + 1e-5f);
        float z = (Y[i] - m) * sc * G[c] + B[c];
        Z[i] = fmaxf(z, 0.0f);
    }
}

// ---------------- alignment ----------------
// Replicate the jitted reference chain op-by-op:
//   ref = fl(fl(c+0.5)*0.2f) + pc_min      (per-op f32, kept)
//   d   = ref - pc_min                     (round trip kept, NOT elided)
//   q   = d * fl(1/vs)                     (XLA rewrites div-by-const to mul-by-recip;
//                                           fl(1/0.1f)=10.0f, fl(1/0.4f)=2.5f exactly)
//   idx = clip(floor(q))
__device__ __forceinline__ int lower_bound_i32(const int* __restrict__ a, int n, int key) {
    int lo = 0, hi = n;
    while (lo < hi) {
        int mid = (lo + hi) >> 1;
        if (a[mid] < key) lo = mid + 1; else hi = mid;
    }
    return lo;
}

__global__ void align_kernel(const int* __restrict__ uc1, int M1,
                             const int* __restrict__ keys0, int M0,
                             const int* __restrict__ keys2, int M2) {
    int i = blockIdx.x * blockDim.x + threadIdx.x;
    if (i >= M1) return;
    int b  = uc1[4 * i + 0];
    int cx = uc1[4 * i + 1];
    int cy = uc1[4 * i + 2];
    int cz = uc1[4 * i + 3];
    // ref_centers = (c + 0.5) * vs1 + pc_min, each op rounded separately
    float rx = __fadd_rn(__fmul_rn(__fadd_rn((float)cx, 0.5f), 0.2f), -50.0f);
    float ry = __fadd_rn(__fmul_rn(__fadd_rn((float)cy, 0.5f), 0.2f), -50.0f);
    float rz = __fadd_rn(__fmul_rn(__fadd_rn((float)cz, 0.5f), 0.2f), -3.0f);
    // d = ref - pc_min (kept), then multiply by exact f32 reciprocal of vs
    float dx = __fsub_rn(rx, -50.0f);
    float dy = __fsub_rn(ry, -50.0f);
    float dz = __fsub_rn(rz, -3.0f);
    // scale 0: vs=0.1 -> *10.0f, clip to (999,999,59)
    {
        int ix = (int)floorf(__fmul_rn(dx, 10.0f)); ix = min(max(ix, 0), 999);
        int iy = (int)floorf(__fmul_rn(dy, 10.0f)); iy = min(max(iy, 0), 999);
        int iz = (int)floorf(__fmul_rn(dz, 10.0f)); iz = min(max(iz, 0), 59);
        int k = b * 1000000000 + ix * 1000000 + iy * 1000 + iz;
        int lo = lower_bound_i32(keys0, M0, k);
        int idx = min(lo, M0 - 1); if (idx < 0) idx = 0;
        g_idx0[i] = (keys0[idx] == k) ? idx : -1;
    }
    // scale 2: vs=0.4 -> *2.5f, clip to (249,249,14)
    {
        int ix = (int)floorf(__fmul_rn(dx, 2.5f)); ix = min(max(ix, 0), 249);
        int iy = (int)floorf(__fmul_rn(dy, 2.5f)); iy = min(max(iy, 0), 249);
        int iz = (int)floorf(__fmul_rn(dz, 2.5f)); iz = min(max(iz, 0), 14);
        int k = b * 1000000000 + ix * 1000000 + iy * 1000 + iz;
        int lo = lower_bound_i32(keys2, M2, k);
        int idx = min(lo, M2 - 1); if (idx < 0) idx = 0;
        g_idx2[i] = (keys2[idx] == k) ? idx : -1;
    }
}

// ---------------- build fused [M1,768] = [aligned0 | feat1 | aligned2] ----------------
__global__ void fuse_kernel(int M1) {
    size_t total = (size_t)M1 * 768;
    size_t stride = (size_t)gridDim.x * blockDim.x;
    const float* f0 = g_feat;
    const float* f1 = g_feat + (size_t)MAXM * 256;
    const float* f2 = g_feat + (size_t)2 * MAXM * 256;
    for (size_t t = (size_t)blockIdx.x * blockDim.x + threadIdx.x; t < total; t += stride) {
        size_t r = t / 768;
        int c = (int)(t % 768);
        float v;
        if (c < 256) {
            int j = g_idx0[r];
            v = (j >= 0) ? f0[(size_t)j * 256 + c] : 0.0f;
        } else if (c < 512) {
            v = f1[r * 256 + (c - 256)];
        } else {
            int j = g_idx2[r];
            v = (j >= 0) ? f2[(size_t)j * 256 + (c - 512)] : 0.0f;
        }
        g_fused[t] = v;
    }
}

// ---------------- host orchestration ----------------
extern "C" void kernel_launch(void* const* d_in, const int* in_sizes, int n_in,
                              void* d_out, int out_size) {
    (void)n_in; (void)out_size;
    const float* points = (const float*)d_in[0];
    const float* W1 = (const float*)d_in[1];
    const float* G1 = (const float*)d_in[2];
    const float* B1 = (const float*)d_in[3];
    const float* W2 = (const float*)d_in[4];
    const float* G2 = (const float*)d_in[5];
    const float* B2 = (const float*)d_in[6];
    const float* W3 = (const float*)d_in[7];
    const float* G3 = (const float*)d_in[8];
    const float* B3 = (const float*)d_in[9];
    const float* Wf = (const float*)d_in[10];
    const float* Gf = (const float*)d_in[11];
    const float* Bf = (const float*)d_in[12];
    const int* inv0 = (const int*)d_in[13];
    const int* inv1 = (const int*)d_in[14];
    const int* inv2 = (const int*)d_in[15];
    const int* keys0 = (const int*)d_in[16];
    const int* keys2 = (const int*)d_in[17];
    const int* uc1   = (const int*)d_in[18];

    int N  = in_sizes[0] / 4;
    int M0 = in_sizes[16];
    int M2 = in_sizes[17];
    int M1 = in_sizes[18] / 4;
    int Ms[3] = {M0, M1, M2};

    float *x, *t64, *t128, *feat, *fused, *y, *stats;
    cudaGetSymbolAddress((void**)&x,     g_x);
    cudaGetSymbolAddress((void**)&t64,   g_t64);
    cudaGetSymbolAddress((void**)&t128,  g_t128);
    cudaGetSymbolAddress((void**)&feat,  g_feat);
    cudaGetSymbolAddress((void**)&fused, g_fused);
    cudaGetSymbolAddress((void**)&y,     g_y);
    cudaGetSymbolAddress((void**)&stats, g_stats);

    zero_kernel<<<2048, 256>>>();
    scatter_kernel<<<(N + 255) / 256, 256>>>(points, inv0, inv1, inv2, N);

    const float* Wl[3] = {W1, W2, W3};
    const float* Gl[3] = {G1, G2, G3};
    const float* Bl[3] = {B1, B2, B3};
    const int Cin[4]  = {4, 64, 128, 256};

    for (int s = 0; s < 3; s++) {
        int M = Ms[s];
        mean_kernel<<<(M + 255) / 256, 256>>>(s, M);
        const float* xin = x + (size_t)s * MAXM * 4;
        float* fs = feat + (size_t)s * MAXM * 256;
        float* outs[3] = {t64, t128, fs};
        const float* ins[3] = {xin, t64, t128};
        for (int l = 0; l < 3; l++) {
            int K = Cin[l], C = Cin[l + 1];
            float* O = outs[l];
            dim3 grid((C + 63) / 64, (M + 63) / 64);
            sgemm_nt<<<grid, 256>>>(ins[l], Wl[l] + (size_t)s * C * K, O, M, C, K);
            float* st = stats + (size_t)(s * 3 + l) * 1536;
            stats_kernel<<<512, 256>>>(O, M, C, st);
            bnrelu_kernel<<<2048, 256>>>(O, O, M, C, st,
                                         Gl[l] + (size_t)s * C, Bl[l] + (size_t)s * C);
        }
    }

    align_kernel<<<(M1 + 255) / 256, 256>>>(uc1, M1, keys0, M0, keys2, M2);
    fuse_kernel<<<4096, 256>>>(M1);

    {
        dim3 grid((256 + 63) / 64, (M1 + 63) / 64);
        sgemm_nt<<<grid, 256>>>(fused, Wf, y, M1, 256, 768);
        float* st = stats + (size_t)9 * 1536;
        stats_kernel<<<512, 256>>>(y, M1, 256, st);
        bnrelu_kernel<<<4096, 256>>>(y, (float*)d_out, M1, 256, st, Gf, Bf);
    }
}

// round 5
// speedup vs baseline: 1.9862x; 1.9862x over previous
#include <cuda_runtime.h>
#include <math.h>

#define MAXM 200000

// ---------------- static device scratch (no allocations allowed) ----------------
__device__ float g_acc[3 * MAXM * 5];              // per-scale [M,4] sums + count
__device__ float g_x[3 * MAXM * 4];                // scatter-mean outputs
__device__ float g_t64[MAXM * 64];                 // layer1 out (reused per scale)
__device__ float g_t128[MAXM * 128];               // layer2 out (reused per scale)
__device__ float g_feat[(size_t)3 * MAXM * 256];   // layer3 out per scale (kept)
__device__ float g_fused[(size_t)MAXM * 768];      // concat features
__device__ float g_y[(size_t)MAXM * 256];          // final pre-BN
__device__ float g_stats[10 * 1536];               // 10 BN slots: [sum(C), sumsq(C)]
__device__ int   g_idx0[MAXM];
__device__ int   g_idx2[MAXM];

// ---------------- zero scratch ----------------
__global__ void zero_kernel() {
    const size_t n1 = (size_t)3 * MAXM * 5;
    const size_t n2 = 10 * 1536;
    const size_t total = n1 + n2;
    const size_t stride = (size_t)gridDim.x * blockDim.x;
    for (size_t i = (size_t)blockIdx.x * blockDim.x + threadIdx.x; i < total; i += stride) {
        if (i < n1) g_acc[i] = 0.0f;
        else        g_stats[i - n1] = 0.0f;
    }
}

// ---------------- scatter (sum + count) for all 3 scales ----------------
__global__ void scatter_kernel(const float* __restrict__ pts,
                               const int* __restrict__ inv0,
                               const int* __restrict__ inv1,
                               const int* __restrict__ inv2, int N) {
    int i = blockIdx.x * blockDim.x + threadIdx.x;
    if (i >= N) return;
    float4 p = reinterpret_cast<const float4*>(pts)[i];
    int m0 = inv0[i], m1 = inv1[i], m2 = inv2[i];
    float* a0 = g_acc + (size_t)m0 * 5;
    float* a1 = g_acc + (size_t)MAXM * 5 + (size_t)m1 * 5;
    float* a2 = g_acc + (size_t)2 * MAXM * 5 + (size_t)m2 * 5;
    atomicAdd(a0 + 0, p.x); atomicAdd(a0 + 1, p.y); atomicAdd(a0 + 2, p.z); atomicAdd(a0 + 3, p.w); atomicAdd(a0 + 4, 1.0f);
    atomicAdd(a1 + 0, p.x); atomicAdd(a1 + 1, p.y); atomicAdd(a1 + 2, p.z); atomicAdd(a1 + 3, p.w); atomicAdd(a1 + 4, 1.0f);
    atomicAdd(a2 + 0, p.x); atomicAdd(a2 + 1, p.y); atomicAdd(a2 + 2, p.z); atomicAdd(a2 + 3, p.w); atomicAdd(a2 + 4, 1.0f);
}

// ---------------- finish mean: x = sum / max(cnt,1) ----------------
__global__ void mean_kernel(int s, int M) {
    int i = blockIdx.x * blockDim.x + threadIdx.x;
    if (i >= M) return;
    const float* a = g_acc + (size_t)s * MAXM * 5 + (size_t)i * 5;
    float c = fmaxf(a[4], 1.0f);
    float* x = g_x + (size_t)s * MAXM * 4 + (size_t)i * 4;
    x[0] = a[0] / c; x[1] = a[1] / c; x[2] = a[2] / c; x[3] = a[3] / c;
}

// ---------------- packed f32x2 helpers (Blackwell FFMA2) ----------------
__device__ __forceinline__ unsigned long long pk2(float lo, float hi) {
    unsigned long long r;
    asm("mov.b64 %0, {%1, %2};" : "=l"(r) : "f"(lo), "f"(hi));
    return r;
}
__device__ __forceinline__ void fma2(unsigned long long& d, unsigned long long a, unsigned long long b) {
    asm("fma.rn.f32x2 %0, %1, %2, %0;" : "+l"(d) : "l"(a), "l"(b));
}
__device__ __forceinline__ void upk2(unsigned long long v, float& lo, float& hi) {
    asm("mov.b64 {%0, %1}, %2;" : "=f"(lo), "=f"(hi) : "l"(v));
}

// ---------------- NT SGEMM + fused column stats ----------------
// C[m,n] = sum_k A[m,k]*W[n,k]; also st[n] += col sums, st[N+n] += col sumsq.
// BMxBN tile, BK=16, 8x8 microtile, (BM/8)*(BN/8) threads, f32x2 packed FMAs.
// Requires: K % 4 == 0, N % BN == 0, A/W rows 16B-aligned (K % 4 == 0 ensures it).
template<int BM, int BN>
__global__ void __launch_bounds__((BM / 8) * (BN / 8))
sgemm_nt_stats(const float* __restrict__ A, const float* __restrict__ W,
               float* __restrict__ C, int M, int N, int K,
               float* __restrict__ st) {
    constexpr int BK = 16;
    constexpr int NT = (BM / 8) * (BN / 8);
    __shared__ float As[BK][BM + 4];
    __shared__ float Ws[BK][BN + 4];
    __shared__ float s_sum[BN];
    __shared__ float s_sq[BN];

    int tid = threadIdx.x;
    int bn = blockIdx.x * BN;
    int bm = blockIdx.y * BM;
    int tx = tid % (BN / 8);
    int ty = tid / (BN / 8);

    for (int c = tid; c < BN; c += NT) { s_sum[c] = 0.0f; s_sq[c] = 0.0f; }

    unsigned long long acc[8][4];
    #pragma unroll
    for (int i = 0; i < 8; i++)
        #pragma unroll
        for (int j = 0; j < 4; j++)
            acc[i][j] = 0ull;   // (+0.f, +0.f)

    for (int k0 = 0; k0 < K; k0 += BK) {
        #pragma unroll
        for (int v = tid; v < BM * BK / 4; v += NT) {
            int m = v >> 2, kq = (v & 3) * 4;
            int gm = bm + m, gk = k0 + kq;
            float4 val = make_float4(0.f, 0.f, 0.f, 0.f);
            if (gm < M && gk + 3 < K)
                val = *reinterpret_cast<const float4*>(A + (size_t)gm * K + gk);
            As[kq + 0][m] = val.x; As[kq + 1][m] = val.y;
            As[kq + 2][m] = val.z; As[kq + 3][m] = val.w;
        }
        #pragma unroll
        for (int v = tid; v < BN * BK / 4; v += NT) {
            int n = v >> 2, kq = (v & 3) * 4;
            int gn = bn + n, gk = k0 + kq;
            float4 val = make_float4(0.f, 0.f, 0.f, 0.f);
            if (gn < N && gk + 3 < K)
                val = *reinterpret_cast<const float4*>(W + (size_t)gn * K + gk);
            Ws[kq + 0][n] = val.x; Ws[kq + 1][n] = val.y;
            Ws[kq + 2][n] = val.z; Ws[kq + 3][n] = val.w;
        }
        __syncthreads();
        #pragma unroll
        for (int k = 0; k < BK; k++) {
            float4 a0 = *reinterpret_cast<const float4*>(&As[k][ty * 8]);
            float4 a1 = *reinterpret_cast<const float4*>(&As[k][ty * 8 + 4]);
            float4 b0 = *reinterpret_cast<const float4*>(&Ws[k][tx * 8]);
            float4 b1 = *reinterpret_cast<const float4*>(&Ws[k][tx * 8 + 4]);
            unsigned long long bp0 = pk2(b0.x, b0.y), bp1 = pk2(b0.z, b0.w);
            unsigned long long bp2 = pk2(b1.x, b1.y), bp3 = pk2(b1.z, b1.w);
            float av[8] = {a0.x, a0.y, a0.z, a0.w, a1.x, a1.y, a1.z, a1.w};
            #pragma unroll
            for (int i = 0; i < 8; i++) {
                unsigned long long ap = pk2(av[i], av[i]);
                fma2(acc[i][0], ap, bp0);
                fma2(acc[i][1], ap, bp1);
                fma2(acc[i][2], ap, bp2);
                fma2(acc[i][3], ap, bp3);
            }
        }
        __syncthreads();
    }

    // epilogue: store C + per-block column stats
    float csum[8] = {0, 0, 0, 0, 0, 0, 0, 0};
    float csq[8]  = {0, 0, 0, 0, 0, 0, 0, 0};
    #pragma unroll
    for (int i = 0; i < 8; i++) {
        int gm = bm + ty * 8 + i;
        float vals[8];
        #pragma unroll
        for (int j = 0; j < 4; j++) upk2(acc[i][j], vals[2 * j], vals[2 * j + 1]);
        if (gm < M) {
            float* crow = C + (size_t)gm * N + bn + tx * 8;
            *reinterpret_cast<float4*>(crow)     = make_float4(vals[0], vals[1], vals[2], vals[3]);
            *reinterpret_cast<float4*>(crow + 4) = make_float4(vals[4], vals[5], vals[6], vals[7]);
            #pragma unroll
            for (int j = 0; j < 8; j++) { csum[j] += vals[j]; csq[j] += vals[j] * vals[j]; }
        }
    }
    #pragma unroll
    for (int j = 0; j < 8; j++) {
        atomicAdd(&s_sum[tx * 8 + j], csum[j]);
        atomicAdd(&s_sq[tx * 8 + j], csq[j]);
    }
    __syncthreads();
    for (int c = tid; c < BN; c += NT) {
        atomicAdd(&st[bn + c],     s_sum[c]);
        atomicAdd(&st[N + bn + c], s_sq[c]);
    }
}

// ---------------- BN (training-mode, biased var) + ReLU ----------------
__global__ void bnrelu_kernel(const float* __restrict__ Y, float* __restrict__ Z,
                              int M, int C, const float* __restrict__ st,
                              const float* __restrict__ G, const float* __restrict__ B) {
    size_t total = (size_t)M * C;
    size_t stride = (size_t)gridDim.x * blockDim.x;
    float invM = 1.0f / (float)M;
    for (size_t i = (size_t)blockIdx.x * blockDim.x + threadIdx.x; i < total; i += stride) {
        int c = (int)(i % C);
        float m = st[c] * invM;
        float v = st[C + c] * invM - m * m;
        float sc = rsqrtf(fmaxf(v, 0.0f) + 1e-5f);
        float z = (Y[i] - m) * sc * G[c] + B[c];
        Z[i] = fmaxf(z, 0.0f);
    }
}

// ---------------- alignment (matches jitted reference bit-exactly) ----------------
__device__ __forceinline__ int lower_bound_i32(const int* __restrict__ a, int n, int key) {
    int lo = 0, hi = n;
    while (lo < hi) {
        int mid = (lo + hi) >> 1;
        if (a[mid] < key) lo = mid + 1; else hi = mid;
    }
    return lo;
}

__global__ void align_kernel(const int* __restrict__ uc1, int M1,
                             const int* __restrict__ keys0, int M0,
                             const int* __restrict__ keys2, int M2) {
    int i = blockIdx.x * blockDim.x + threadIdx.x;
    if (i >= M1) return;
    int b  = uc1[4 * i + 0];
    int cx = uc1[4 * i + 1];
    int cy = uc1[4 * i + 2];
    int cz = uc1[4 * i + 3];
    float rx = __fadd_rn(__fmul_rn(__fadd_rn((float)cx, 0.5f), 0.2f), -50.0f);
    float ry = __fadd_rn(__fmul_rn(__fadd_rn((float)cy, 0.5f), 0.2f), -50.0f);
    float rz = __fadd_rn(__fmul_rn(__fadd_rn((float)cz, 0.5f), 0.2f), -3.0f);
    float dx = __fsub_rn(rx, -50.0f);
    float dy = __fsub_rn(ry, -50.0f);
    float dz = __fsub_rn(rz, -3.0f);
    {
        int ix = (int)floorf(__fmul_rn(dx, 10.0f)); ix = min(max(ix, 0), 999);
        int iy = (int)floorf(__fmul_rn(dy, 10.0f)); iy = min(max(iy, 0), 999);
        int iz = (int)floorf(__fmul_rn(dz, 10.0f)); iz = min(max(iz, 0), 59);
        int k = b * 1000000000 + ix * 1000000 + iy * 1000 + iz;
        int lo = lower_bound_i32(keys0, M0, k);
        int idx = min(lo, M0 - 1); if (idx < 0) idx = 0;
        g_idx0[i] = (keys0[idx] == k) ? idx : -1;
    }
    {
        int ix = (int)floorf(__fmul_rn(dx, 2.5f)); ix = min(max(ix, 0), 249);
        int iy = (int)floorf(__fmul_rn(dy, 2.5f)); iy = min(max(iy, 0), 249);
        int iz = (int)floorf(__fmul_rn(dz, 2.5f)); iz = min(max(iz, 0), 14);
        int k = b * 1000000000 + ix * 1000000 + iy * 1000 + iz;
        int lo = lower_bound_i32(keys2, M2, k);
        int idx = min(lo, M2 - 1); if (idx < 0) idx = 0;
        g_idx2[i] = (keys2[idx] == k) ? idx : -1;
    }
}

// ---------------- build fused [M1,768] = [aligned0 | feat1 | aligned2] ----------------
__global__ void fuse_kernel(int M1) {
    size_t total = (size_t)M1 * 768;
    size_t stride = (size_t)gridDim.x * blockDim.x;
    const float* f0 = g_feat;
    const float* f1 = g_feat + (size_t)MAXM * 256;
    const float* f2 = g_feat + (size_t)2 * MAXM * 256;
    for (size_t t = (size_t)blockIdx.x * blockDim.x + threadIdx.x; t < total; t += stride) {
        size_t r = t / 768;
        int c = (int)(t % 768);
        float v;
        if (c < 256) {
            int j = g_idx0[r];
            v = (j >= 0) ? f0[(size_t)j * 256 + c] : 0.0f;
        } else if (c < 512) {
            v = f1[r * 256 + (c - 256)];
        } else {
            int j = g_idx2[r];
            v = (j >= 0) ? f2[(size_t)j * 256 + (c - 512)] : 0.0f;
        }
        g_fused[t] = v;
    }
}

// ---------------- host orchestration ----------------
extern "C" void kernel_launch(void* const* d_in, const int* in_sizes, int n_in,
                              void* d_out, int out_size) {
    (void)n_in; (void)out_size;
    const float* points = (const float*)d_in[0];
    const float* W1 = (const float*)d_in[1];
    const float* G1 = (const float*)d_in[2];
    const float* B1 = (const float*)d_in[3];
    const float* W2 = (const float*)d_in[4];
    const float* G2 = (const float*)d_in[5];
    const float* B2 = (const float*)d_in[6];
    const float* W3 = (const float*)d_in[7];
    const float* G3 = (const float*)d_in[8];
    const float* B3 = (const float*)d_in[9];
    const float* Wf = (const float*)d_in[10];
    const float* Gf = (const float*)d_in[11];
    const float* Bf = (const float*)d_in[12];
    const int* inv0 = (const int*)d_in[13];
    const int* inv1 = (const int*)d_in[14];
    const int* inv2 = (const int*)d_in[15];
    const int* keys0 = (const int*)d_in[16];
    const int* keys2 = (const int*)d_in[17];
    const int* uc1   = (const int*)d_in[18];

    int N  = in_sizes[0] / 4;
    int M0 = in_sizes[16];
    int M2 = in_sizes[17];
    int M1 = in_sizes[18] / 4;
    int Ms[3] = {M0, M1, M2};

    float *x, *t64, *t128, *feat, *fused, *y, *stats;
    cudaGetSymbolAddress((void**)&x,     g_x);
    cudaGetSymbolAddress((void**)&t64,   g_t64);
    cudaGetSymbolAddress((void**)&t128,  g_t128);
    cudaGetSymbolAddress((void**)&feat,  g_feat);
    cudaGetSymbolAddress((void**)&fused, g_fused);
    cudaGetSymbolAddress((void**)&y,     g_y);
    cudaGetSymbolAddress((void**)&stats, g_stats);

    zero_kernel<<<2048, 256>>>();
    scatter_kernel<<<(N + 255) / 256, 256>>>(points, inv0, inv1, inv2, N);

    const float* Wl[3] = {W1, W2, W3};
    const float* Gl[3] = {G1, G2, G3};
    const float* Bl[3] = {B1, B2, B3};
    const int Cin[4]  = {4, 64, 128, 256};

    for (int s = 0; s < 3; s++) {
        int M = Ms[s];
        mean_kernel<<<(M + 255) / 256, 256>>>(s, M);
        const float* xin = x + (size_t)s * MAXM * 4;
        float* fs = feat + (size_t)s * MAXM * 256;
        float* outs[3] = {t64, t128, fs};
        const float* ins[3] = {xin, t64, t128};
        for (int l = 0; l < 3; l++) {
            int K = Cin[l], C = Cin[l + 1];
            float* O = outs[l];
            float* st = stats + (size_t)(s * 3 + l) * 1536;
            if (C == 64) {
                dim3 grid(1, (M + 127) / 128);
                sgemm_nt_stats<128, 64><<<grid, 128>>>(ins[l], Wl[l] + (size_t)s * C * K, O, M, C, K, st);
            } else {
                dim3 grid(C / 128, (M + 127) / 128);
                sgemm_nt_stats<128, 128><<<grid, 256>>>(ins[l], Wl[l] + (size_t)s * C * K, O, M, C, K, st);
            }
            bnrelu_kernel<<<2048, 256>>>(O, O, M, C, st,
                                         Gl[l] + (size_t)s * C, Bl[l] + (size_t)s * C);
        }
    }

    align_kernel<<<(M1 + 255) / 256, 256>>>(uc1, M1, keys0, M0, keys2, M2);
    fuse_kernel<<<4096, 256>>>(M1);

    {
        float* st = stats + (size_t)9 * 1536;
        dim3 grid(256 / 128, (M1 + 127) / 128);
        sgemm_nt_stats<128, 128><<<grid, 256>>>(fused, Wf, y, M1, 256, 768, st);
        bnrelu_kernel<<<4096, 256>>>(y, (float*)d_out, M1, 256, st, Gf, Bf);
    }
}

// round 6
// speedup vs baseline: 1.9985x; 1.0062x over previous
#include <cuda_runtime.h>
#include <math.h>

#define MAXM 200000

// ---------------- static device scratch ----------------
__device__ float g_acc[3 * MAXM * 5];
__device__ float g_x[3 * MAXM * 4];
__device__ float g_t64[(size_t)3 * MAXM * 64];    // layer1 out, pre-BN
__device__ float g_t128[(size_t)3 * MAXM * 128];  // layer2 out, pre-BN
__device__ float g_feat[(size_t)3 * MAXM * 256];  // layer3 out, pre-BN
__device__ float g_y[(size_t)MAXM * 256];         // final pre-BN
__device__ float g_stats[10 * 1536];              // slots: L1 s0..2, L2 s0..2, L3 s0..2, final
__device__ int   g_idx0[MAXM];
__device__ int   g_idx2[MAXM];

// ---------------- zero scratch ----------------
__global__ void zero_kernel() {
    const size_t n1 = (size_t)3 * MAXM * 5;
    const size_t total = n1 + 10 * 1536;
    const size_t stride = (size_t)gridDim.x * blockDim.x;
    for (size_t i = (size_t)blockIdx.x * blockDim.x + threadIdx.x; i < total; i += stride) {
        if (i < n1) g_acc[i] = 0.0f;
        else        g_stats[i - n1] = 0.0f;
    }
}

// ---------------- scatter (sum + count) for all 3 scales ----------------
__global__ void scatter_kernel(const float* __restrict__ pts,
                               const int* __restrict__ inv0,
                               const int* __restrict__ inv1,
                               const int* __restrict__ inv2, int N) {
    int i = blockIdx.x * blockDim.x + threadIdx.x;
    if (i >= N) return;
    float4 p = reinterpret_cast<const float4*>(pts)[i];
    int m0 = inv0[i], m1 = inv1[i], m2 = inv2[i];
    float* a0 = g_acc + (size_t)m0 * 5;
    float* a1 = g_acc + (size_t)MAXM * 5 + (size_t)m1 * 5;
    float* a2 = g_acc + (size_t)2 * MAXM * 5 + (size_t)m2 * 5;
    atomicAdd(a0 + 0, p.x); atomicAdd(a0 + 1, p.y); atomicAdd(a0 + 2, p.z); atomicAdd(a0 + 3, p.w); atomicAdd(a0 + 4, 1.0f);
    atomicAdd(a1 + 0, p.x); atomicAdd(a1 + 1, p.y); atomicAdd(a1 + 2, p.z); atomicAdd(a1 + 3, p.w); atomicAdd(a1 + 4, 1.0f);
    atomicAdd(a2 + 0, p.x); atomicAdd(a2 + 1, p.y); atomicAdd(a2 + 2, p.z); atomicAdd(a2 + 3, p.w); atomicAdd(a2 + 4, 1.0f);
}

// ---------------- finish mean ----------------
__global__ void mean_kernel(int s, int M) {
    int i = blockIdx.x * blockDim.x + threadIdx.x;
    if (i >= M) return;
    const float* a = g_acc + (size_t)s * MAXM * 5 + (size_t)i * 5;
    float c = fmaxf(a[4], 1.0f);
    float* x = g_x + (size_t)s * MAXM * 4 + (size_t)i * 4;
    x[0] = a[0] / c; x[1] = a[1] / c; x[2] = a[2] / c; x[3] = a[3] / c;
}

// ---------------- packed f32x2 helpers ----------------
__device__ __forceinline__ unsigned long long pk2(float lo, float hi) {
    unsigned long long r;
    asm("mov.b64 %0, {%1, %2};" : "=l"(r) : "f"(lo), "f"(hi));
    return r;
}
__device__ __forceinline__ void fma2(unsigned long long& d, unsigned long long a, unsigned long long b) {
    asm("fma.rn.f32x2 %0, %1, %2, %0;" : "+l"(d) : "l"(a), "l"(b));
}
__device__ __forceinline__ void upk2(unsigned long long v, float& lo, float& hi) {
    asm("mov.b64 {%0, %1}, %2;" : "=f"(lo), "=f"(hi) : "l"(v));
}

// ---------------- GEMM: double-buffered, scale-batched, fused stats, optional BN-on-load ----------
// MODE 0: plain A load. MODE 1: A = relu(bn(raw)) using prev stats (prev C == K).
// MODE 2: gather A from g_feat via g_idx0/g_idx2, apply per-segment relu(bn()) (prev C == 256).
// C[m,n] = sum_k A[m,k]*W[n,k]; epilogue accumulates column sum/sumsq into st.
template<int BM, int BN, int MODE>
__global__ void __launch_bounds__((BM / 8) * (BN / 8))
gemm_dbuf(const float* __restrict__ Abase, size_t Astr,
          const float* __restrict__ Wbase, size_t Wstr,
          float* __restrict__ Cbase, size_t Cstr,
          int3 Ms, int N, int K,
          float* __restrict__ stbase,
          const float* __restrict__ pstB,   // prev-layer stats base (stride 1536)
          const float* __restrict__ pGB,    // prev gamma base (stride pGstr)
          const float* __restrict__ pBB,    // prev beta base
          int pGstr) {
    constexpr int BK = 16;
    constexpr int NT = (BM / 8) * (BN / 8);
    constexpr int NA = (BM * BK / 4) / NT;
    constexpr int NB = (BN * BK / 4) / NT;

    int s = blockIdx.z;
    int M = (MODE == 2) ? Ms.y : ((s == 0) ? Ms.x : (s == 1) ? Ms.y : Ms.z);
    int bm = blockIdx.y * BM;
    if (bm >= M) return;

    const float* A = Abase + (size_t)s * Astr;
    const float* W = Wbase + (size_t)s * Wstr;
    float* C = Cbase + (size_t)s * Cstr;
    float* st = stbase + (size_t)s * 1536;

    // BN-on-load constants (MODE 1)
    const float* pst = (MODE == 1) ? (pstB + (size_t)s * 1536) : pstB;
    const float* pG  = (MODE == 1) ? (pGB + (size_t)s * pGstr) : pGB;
    const float* pB  = (MODE == 1) ? (pBB + (size_t)s * pGstr) : pBB;
    float iM = (MODE == 1) ? (1.0f / (float)M) : 0.0f;

    int bn = blockIdx.x * BN;
    int tid = threadIdx.x;
    int tx = tid % (BN / 8);
    int ty = tid / (BN / 8);

    __shared__ float As[2][BK][BM + 4];
    __shared__ float Ws[2][BK][BN + 4];
    __shared__ float s_sum[BN];
    __shared__ float s_sq[BN];
    for (int c = tid; c < BN; c += NT) { s_sum[c] = 0.0f; s_sq[c] = 0.0f; }

    float4 ra[NA], rb[NB];
    int ntile = (K + BK - 1) / BK;

    auto loadA = [&](int t) {
        #pragma unroll
        for (int i = 0; i < NA; i++) {
            int v = tid + i * NT;
            int m = v >> 2, kq = (v & 3) * 4;
            int gm = bm + m, gk = t * BK + kq;
            float4 val = make_float4(0.f, 0.f, 0.f, 0.f);
            bool loaded = false;
            int off = 0;
            const float* seg_pst = nullptr; const float* seg_pG = nullptr; const float* seg_pB = nullptr;
            float seg_iM = 0.f;
            if (MODE == 2) {
                if (gm < M && gk + 4 <= K) {
                    int seg = gk >> 8; off = gk & 255;
                    const float* src = nullptr;
                    if (seg == 0) {
                        int j = g_idx0[gm];
                        if (j >= 0) src = g_feat + (size_t)j * 256 + off;
                    } else if (seg == 1) {
                        src = g_feat + (size_t)MAXM * 256 + (size_t)gm * 256 + off;
                    } else {
                        int j = g_idx2[gm];
                        if (j >= 0) src = g_feat + (size_t)2 * MAXM * 256 + (size_t)j * 256 + off;
                    }
                    if (src) {
                        val = *reinterpret_cast<const float4*>(src);
                        loaded = true;
                        seg_pst = pstB + (size_t)seg * 1536;
                        seg_pG = pGB + (size_t)seg * 256;
                        seg_pB = pBB + (size_t)seg * 256;
                        seg_iM = (seg == 0) ? (1.0f / (float)Ms.x)
                               : (seg == 1) ? (1.0f / (float)Ms.y)
                                            : (1.0f / (float)Ms.z);
                    }
                }
                if (loaded) {
                    float vv[4] = {val.x, val.y, val.z, val.w};
                    #pragma unroll
                    for (int c = 0; c < 4; c++) {
                        float m0 = seg_pst[off + c] * seg_iM;
                        float q0 = seg_pst[256 + off + c] * seg_iM;
                        float sc = rsqrtf(fmaxf(q0 - m0 * m0, 0.f) + 1e-5f) * seg_pG[off + c];
                        vv[c] = fmaxf((vv[c] - m0) * sc + seg_pB[off + c], 0.f);
                    }
                    val = make_float4(vv[0], vv[1], vv[2], vv[3]);
                }
            } else {
                if (gm < M && gk + 4 <= K) {
                    val = *reinterpret_cast<const float4*>(A + (size_t)gm * K + gk);
                    loaded = true;
                }
                if (MODE == 1 && loaded) {
                    float vv[4] = {val.x, val.y, val.z, val.w};
                    #pragma unroll
                    for (int c = 0; c < 4; c++) {
                        float m0 = pst[gk + c] * iM;
                        float q0 = pst[K + gk + c] * iM;
                        float sc = rsqrtf(fmaxf(q0 - m0 * m0, 0.f) + 1e-5f) * pG[gk + c];
                        vv[c] = fmaxf((vv[c] - m0) * sc + pB[gk + c], 0.f);
                    }
                    val = make_float4(vv[0], vv[1], vv[2], vv[3]);
                }
            }
            ra[i] = val;
        }
    };
    auto loadB = [&](int t) {
        #pragma unroll
        for (int i = 0; i < NB; i++) {
            int v = tid + i * NT;
            int n = v >> 2, kq = (v & 3) * 4;
            int gn = bn + n, gk = t * BK + kq;
            float4 val = make_float4(0.f, 0.f, 0.f, 0.f);
            if (gn < N && gk + 4 <= K)
                val = *reinterpret_cast<const float4*>(W + (size_t)gn * K + gk);
            rb[i] = val;
        }
    };
    auto storeA = [&](int buf) {
        #pragma unroll
        for (int i = 0; i < NA; i++) {
            int v = tid + i * NT;
            int m = v >> 2, kq = (v & 3) * 4;
            As[buf][kq + 0][m] = ra[i].x; As[buf][kq + 1][m] = ra[i].y;
            As[buf][kq + 2][m] = ra[i].z; As[buf][kq + 3][m] = ra[i].w;
        }
    };
    auto storeB = [&](int buf) {
        #pragma unroll
        for (int i = 0; i < NB; i++) {
            int v = tid + i * NT;
            int n = v >> 2, kq = (v & 3) * 4;
            Ws[buf][kq + 0][n] = rb[i].x; Ws[buf][kq + 1][n] = rb[i].y;
            Ws[buf][kq + 2][n] = rb[i].z; Ws[buf][kq + 3][n] = rb[i].w;
        }
    };

    unsigned long long acc[8][4];
    #pragma unroll
    for (int i = 0; i < 8; i++)
        #pragma unroll
        for (int j = 0; j < 4; j++)
            acc[i][j] = 0ull;

    loadA(0); loadB(0);
    storeA(0); storeB(0);
    __syncthreads();

    for (int t = 0; t < ntile; t++) {
        if (t + 1 < ntile) { loadA(t + 1); loadB(t + 1); }
        int buf = t & 1;
        #pragma unroll
        for (int k = 0; k < BK; k++) {
            float4 a0 = *reinterpret_cast<const float4*>(&As[buf][k][ty * 8]);
            float4 a1 = *reinterpret_cast<const float4*>(&As[buf][k][ty * 8 + 4]);
            float4 b0 = *reinterpret_cast<const float4*>(&Ws[buf][k][tx * 8]);
            float4 b1 = *reinterpret_cast<const float4*>(&Ws[buf][k][tx * 8 + 4]);
            unsigned long long bp0 = pk2(b0.x, b0.y), bp1 = pk2(b0.z, b0.w);
            unsigned long long bp2 = pk2(b1.x, b1.y), bp3 = pk2(b1.z, b1.w);
            float av[8] = {a0.x, a0.y, a0.z, a0.w, a1.x, a1.y, a1.z, a1.w};
            #pragma unroll
            for (int i = 0; i < 8; i++) {
                unsigned long long ap = pk2(av[i], av[i]);
                fma2(acc[i][0], ap, bp0);
                fma2(acc[i][1], ap, bp1);
                fma2(acc[i][2], ap, bp2);
                fma2(acc[i][3], ap, bp3);
            }
        }
        __syncthreads();
        if (t + 1 < ntile) {
            storeA((t + 1) & 1); storeB((t + 1) & 1);
            __syncthreads();
        }
    }

    // epilogue: store C + per-block column stats
    float csum[8] = {0, 0, 0, 0, 0, 0, 0, 0};
    float csq[8]  = {0, 0, 0, 0, 0, 0, 0, 0};
    #pragma unroll
    for (int i = 0; i < 8; i++) {
        int gm = bm + ty * 8 + i;
        float vals[8];
        #pragma unroll
        for (int j = 0; j < 4; j++) upk2(acc[i][j], vals[2 * j], vals[2 * j + 1]);
        if (gm < M) {
            float* crow = C + (size_t)gm * N + bn + tx * 8;
            *reinterpret_cast<float4*>(crow)     = make_float4(vals[0], vals[1], vals[2], vals[3]);
            *reinterpret_cast<float4*>(crow + 4) = make_float4(vals[4], vals[5], vals[6], vals[7]);
            #pragma unroll
            for (int j = 0; j < 8; j++) { csum[j] += vals[j]; csq[j] += vals[j] * vals[j]; }
        }
    }
    #pragma unroll
    for (int j = 0; j < 8; j++) {
        atomicAdd(&s_sum[tx * 8 + j], csum[j]);
        atomicAdd(&s_sq[tx * 8 + j], csq[j]);
    }
    __syncthreads();
    for (int c = tid; c < BN; c += NT) {
        atomicAdd(&st[bn + c],     s_sum[c]);
        atomicAdd(&st[N + bn + c], s_sq[c]);
    }
}

// ---------------- BN + ReLU (final output only) ----------------
__global__ void bnrelu_kernel(const float* __restrict__ Y, float* __restrict__ Z,
                              int M, int C, const float* __restrict__ st,
                              const float* __restrict__ G, const float* __restrict__ B) {
    size_t total = (size_t)M * C;
    size_t stride = (size_t)gridDim.x * blockDim.x;
    float invM = 1.0f / (float)M;
    for (size_t i = (size_t)blockIdx.x * blockDim.x + threadIdx.x; i < total; i += stride) {
        int c = (int)(i % C);
        float m = st[c] * invM;
        float v = st[C + c] * invM - m * m;
        float sc = rsqrtf(fmaxf(v, 0.0f) + 1e-5f);
        float z = (Y[i] - m) * sc * G[c] + B[c];
        Z[i] = fmaxf(z, 0.0f);
    }
}

// ---------------- alignment (matches jitted reference bit-exactly) ----------------
__device__ __forceinline__ int lower_bound_i32(const int* __restrict__ a, int n, int key) {
    int lo = 0, hi = n;
    while (lo < hi) {
        int mid = (lo + hi) >> 1;
        if (a[mid] < key) lo = mid + 1; else hi = mid;
    }
    return lo;
}

__global__ void align_kernel(const int* __restrict__ uc1, int M1,
                             const int* __restrict__ keys0, int M0,
                             const int* __restrict__ keys2, int M2) {
    int i = blockIdx.x * blockDim.x + threadIdx.x;
    if (i >= M1) return;
    int b  = uc1[4 * i + 0];
    int cx = uc1[4 * i + 1];
    int cy = uc1[4 * i + 2];
    int cz = uc1[4 * i + 3];
    float rx = __fadd_rn(__fmul_rn(__fadd_rn((float)cx, 0.5f), 0.2f), -50.0f);
    float ry = __fadd_rn(__fmul_rn(__fadd_rn((float)cy, 0.5f), 0.2f), -50.0f);
    float rz = __fadd_rn(__fmul_rn(__fadd_rn((float)cz, 0.5f), 0.2f), -3.0f);
    float dx = __fsub_rn(rx, -50.0f);
    float dy = __fsub_rn(ry, -50.0f);
    float dz = __fsub_rn(rz, -3.0f);
    {
        int ix = (int)floorf(__fmul_rn(dx, 10.0f)); ix = min(max(ix, 0), 999);
        int iy = (int)floorf(__fmul_rn(dy, 10.0f)); iy = min(max(iy, 0), 999);
        int iz = (int)floorf(__fmul_rn(dz, 10.0f)); iz = min(max(iz, 0), 59);
        int k = b * 1000000000 + ix * 1000000 + iy * 1000 + iz;
        int lo = lower_bound_i32(keys0, M0, k);
        int idx = min(lo, M0 - 1); if (idx < 0) idx = 0;
        g_idx0[i] = (keys0[idx] == k) ? idx : -1;
    }
    {
        int ix = (int)floorf(__fmul_rn(dx, 2.5f)); ix = min(max(ix, 0), 249);
        int iy = (int)floorf(__fmul_rn(dy, 2.5f)); iy = min(max(iy, 0), 249);
        int iz = (int)floorf(__fmul_rn(dz, 2.5f)); iz = min(max(iz, 0), 14);
        int k = b * 1000000000 + ix * 1000000 + iy * 1000 + iz;
        int lo = lower_bound_i32(keys2, M2, k);
        int idx = min(lo, M2 - 1); if (idx < 0) idx = 0;
        g_idx2[i] = (keys2[idx] == k) ? idx : -1;
    }
}

// ---------------- host orchestration ----------------
extern "C" void kernel_launch(void* const* d_in, const int* in_sizes, int n_in,
                              void* d_out, int out_size) {
    (void)n_in; (void)out_size;
    const float* points = (const float*)d_in[0];
    const float* W1 = (const float*)d_in[1];
    const float* G1 = (const float*)d_in[2];
    const float* B1 = (const float*)d_in[3];
    const float* W2 = (const float*)d_in[4];
    const float* G2 = (const float*)d_in[5];
    const float* B2 = (const float*)d_in[6];
    const float* W3 = (const float*)d_in[7];
    const float* G3 = (const float*)d_in[8];
    const float* B3 = (const float*)d_in[9];
    const float* Wf = (const float*)d_in[10];
    const float* Gf = (const float*)d_in[11];
    const float* Bf = (const float*)d_in[12];
    const int* inv0 = (const int*)d_in[13];
    const int* inv1 = (const int*)d_in[14];
    const int* inv2 = (const int*)d_in[15];
    const int* keys0 = (const int*)d_in[16];
    const int* keys2 = (const int*)d_in[17];
    const int* uc1   = (const int*)d_in[18];

    int N  = in_sizes[0] / 4;
    int M0 = in_sizes[16];
    int M2 = in_sizes[17];
    int M1 = in_sizes[18] / 4;
    int maxM = M0 > M1 ? M0 : M1; if (M2 > maxM) maxM = M2;
    int3 Ms3 = make_int3(M0, M1, M2);

    float *x, *t64, *t128, *feat, *y, *stats;
    cudaGetSymbolAddress((void**)&x,    g_x);
    cudaGetSymbolAddress((void**)&t64,  g_t64);
    cudaGetSymbolAddress((void**)&t128, g_t128);
    cudaGetSymbolAddress((void**)&feat, g_feat);
    cudaGetSymbolAddress((void**)&y,    g_y);
    cudaGetSymbolAddress((void**)&stats, g_stats);

    zero_kernel<<<2048, 256>>>();
    scatter_kernel<<<(N + 255) / 256, 256>>>(points, inv0, inv1, inv2, N);
    mean_kernel<<<(M0 + 255) / 256, 256>>>(0, M0);
    mean_kernel<<<(M1 + 255) / 256, 256>>>(1, M1);
    mean_kernel<<<(M2 + 255) / 256, 256>>>(2, M2);

    // alignment indices (needed only before final GEMM, launch early = overlap-free anyway)
    align_kernel<<<(M1 + 255) / 256, 256>>>(uc1, M1, keys0, M0, keys2, M2);

    int gy = (maxM + 127) / 128;

    // Layer 1: [M,4] -> [M,64], plain A
    gemm_dbuf<128, 64, 0><<<dim3(1, gy, 3), 128>>>(
        x, (size_t)MAXM * 4, W1, 64 * 4, t64, (size_t)MAXM * 64,
        Ms3, 64, 4, stats, nullptr, nullptr, nullptr, 0);

    // Layer 2: [M,64] -> [M,128], BN(layer1) on load
    gemm_dbuf<128, 128, 1><<<dim3(1, gy, 3), 256>>>(
        t64, (size_t)MAXM * 64, W2, 128 * 64, t128, (size_t)MAXM * 128,
        Ms3, 128, 64, stats + 4608, stats, G1, B1, 64);

    // Layer 3: [M,128] -> [M,256], BN(layer2) on load
    gemm_dbuf<128, 128, 1><<<dim3(2, gy, 3), 256>>>(
        t128, (size_t)MAXM * 128, W3, 256 * 128, feat, (size_t)MAXM * 256,
        Ms3, 256, 128, stats + 9216, stats + 4608, G2, B2, 128);

    // Final: gather [M1,768] -> [M1,256], BN(layer3 per segment) on load
    gemm_dbuf<128, 128, 2><<<dim3(2, (M1 + 127) / 128, 1), 256>>>(
        nullptr, 0, Wf, 0, y, 0,
        Ms3, 256, 768, stats + 13824, stats + 9216, G3, B3, 256);

    bnrelu_kernel<<<4096, 256>>>(y, (float*)d_out, M1, 256, stats + 13824, Gf, Bf);
}